// round 2
// baseline (speedup 1.0000x reference)
#include <cuda_runtime.h>
#include <cstdint>

#define HID   100
#define HPAD  104          // h padded so each half is 52 floats (16B-aligned split)
#define GROWS 400
#define TENC  4096
#define TDEC  4096
#define NCLS  6
#define NTH   800          // 25 warps, 2 threads per gate row
#define LOG2E 1.4426950408889634f

typedef unsigned long long ull;

// ---- packed f32x2 helpers (Blackwell FFMA2) ----
__device__ __forceinline__ ull fma2(ull a, ull b, ull c) {
    ull d;
    asm("fma.rn.f32x2 %0, %1, %2, %3;" : "=l"(d) : "l"(a), "l"(b), "l"(c));
    return d;
}
__device__ __forceinline__ ull add2(ull a, ull b) {
    ull d;
    asm("add.rn.f32x2 %0, %1, %2;" : "=l"(d) : "l"(a), "l"(b));
    return d;
}
__device__ __forceinline__ float ex2f(float x) {
    float y; asm("ex2.approx.f32 %0, %1;" : "=f"(y) : "f"(x)); return y;
}
__device__ __forceinline__ float rcpf(float x) {
    float y; asm("rcp.approx.f32 %0, %1;" : "=f"(y) : "f"(x)); return y;
}
__device__ __forceinline__ float tanhf_fast(float x) {
    return 1.0f - 2.0f * rcpf(1.0f + ex2f((2.0f * LOG2E) * x));
}

__global__ void __launch_bounds__(NTH, 1)
lstm_encdec_kernel(const float* __restrict__ x,      // [TENC,3]
                   const int*   __restrict__ y,      // [TDEC]
                   const float* __restrict__ eWih,   // [400,3]
                   const float* __restrict__ eWhh,   // [400,100]
                   const float* __restrict__ ebih,   // [400]
                   const float* __restrict__ ebhh,   // [400]
                   const float* __restrict__ dWih,   // [400,1]
                   const float* __restrict__ dWhh,   // [400,100]
                   const float* __restrict__ dbih,   // [400]
                   const float* __restrict__ dbhh,   // [400]
                   const float* __restrict__ linW,   // [6,100]
                   const float* __restrict__ linb,   // [6]
                   float* __restrict__ out)          // [TDEC,6]
{
    __shared__ __align__(16) float hbuf[2][HPAD];   // double-buffered hidden state
    __shared__ float sg[GROWS];                     // post-activation gates
    __shared__ float slw[NCLS * HID];               // lin_W copy
    __shared__ float slb[NCLS];

    const int tid  = threadIdx.x;
    const int row  = tid >> 1;        // gate row 0..399
    const int hf   = tid & 1;         // which 52-float half of h
    const int wid  = tid >> 5;
    const int lane = tid & 31;

    // ---- init ----
    if (tid < HPAD) { hbuf[0][tid] = 0.0f; hbuf[1][tid] = 0.0f; }
    if (tid < NCLS) { out[(TDEC - 1) * NCLS + tid] = 0.0f; slb[tid] = linb[tid]; }
    for (int i = tid; i < NCLS * HID; i += NTH) slw[i] = linW[i];
    float c = 0.0f;                   // thread j<100 owns cell state c[j]

    // branchless activation constants: rows 200..299 are tanh, rest sigmoid
    const bool is_tanh = (row >= 200 && row < 300);
    const float aa = is_tanh ? 1.0f : 0.0f;
    const float bb = is_tanh ? -2.0f : 1.0f;
    const float kk = is_tanh ? (2.0f * LOG2E) : (-LOG2E);

    // ---- encoder weights -> registers (26 packed f32x2 per thread) ----
    ull w[26];
    float wi0, wi1, wi2, bias;
    {
        const ull* p = (const ull*)(eWhh + row * HID + hf * 52);
        if (hf == 0) {
#pragma unroll
            for (int k = 0; k < 26; ++k) w[k] = p[k];
        } else {
#pragma unroll
            for (int k = 0; k < 24; ++k) w[k] = p[k];
            w[24] = 0ull; w[25] = 0ull;   // pad: cols 100..103
        }
        wi0 = eWih[row * 3 + 0];
        wi1 = eWih[row * 3 + 1];
        wi2 = eWih[row * 3 + 2];
        bias = ebih[row] + ebhh[row];
    }
    __syncthreads();

    int p = 0;

    // ================= encoder: 4096 steps =================
#pragma unroll 1
    for (int t = 0; t < TENC; ++t) {
        const float x0 = x[t * 3 + 0];
        const float x1 = x[t * 3 + 1];
        const float x2 = x[t * 3 + 2];
        {
            const ulonglong2* hp = (const ulonglong2*)(&hbuf[p][hf * 52]);
            ull a0 = 0ull, a1 = 0ull;
#pragma unroll
            for (int m = 0; m < 13; ++m) {
                ulonglong2 hv = hp[m];
                a0 = fma2(w[2 * m],     hv.x, a0);
                a1 = fma2(w[2 * m + 1], hv.y, a1);
            }
            ull s2 = add2(a0, a1);
            float lo, hi;
            asm("mov.b64 {%0, %1}, %2;" : "=f"(lo), "=f"(hi) : "l"(s2));
            float d = lo + hi;
            d += __shfl_xor_sync(0xffffffffu, d, 1);   // combine the two halves
            float g = d + fmaf(wi0, x0, fmaf(wi1, x1, fmaf(wi2, x2, bias)));
            float act = fmaf(bb, rcpf(1.0f + ex2f(kk * g)), aa);
            if (hf == 0) sg[row] = act;
        }
        __syncthreads();   // gates ready
        if (tid < HID) {
            const float gi = sg[tid];
            const float gf = sg[tid + 100];
            const float gg = sg[tid + 200];
            const float go = sg[tid + 300];
            c = fmaf(gf, c, gi * gg);
            hbuf[p ^ 1][tid] = go * tanhf_fast(c);
        }
        __syncthreads();   // h ready
        p ^= 1;
    }

    // ---- decoder weights -> registers (overwrite) ----
    {
        const ull* q = (const ull*)(dWhh + row * HID + hf * 52);
        if (hf == 0) {
#pragma unroll
            for (int k = 0; k < 26; ++k) w[k] = q[k];
        } else {
#pragma unroll
            for (int k = 0; k < 24; ++k) w[k] = q[k];
            w[24] = 0ull; w[25] = 0ull;
        }
        wi0 = dWih[row];
        bias = dbih[row] + dbhh[row];
    }
    // registers only -> no barrier needed

    // logits lane mapping for warp 4: lane = ls*8 + ll
    const int ls = lane >> 3;
    const int ll = lane & 7;

    // ================= decoder: 4096 iterations =================
    // iter s: LSTM step s (s < 4095) overlapped with logits of step s-1
    // (hbuf[p] holds h_{s-1}; logits read it during the tail phase).
#pragma unroll 1
    for (int s = 0; s < TDEC; ++s) {
        const bool work = (s < TDEC - 1);
        if (work) {
            const float yf = (float)__ldg(y + s);   // teacher forcing (ratio==1)
            const ulonglong2* hp = (const ulonglong2*)(&hbuf[p][hf * 52]);
            ull a0 = 0ull, a1 = 0ull;
#pragma unroll
            for (int m = 0; m < 13; ++m) {
                ulonglong2 hv = hp[m];
                a0 = fma2(w[2 * m],     hv.x, a0);
                a1 = fma2(w[2 * m + 1], hv.y, a1);
            }
            ull s2 = add2(a0, a1);
            float lo, hi;
            asm("mov.b64 {%0, %1}, %2;" : "=f"(lo), "=f"(hi) : "l"(s2));
            float d = lo + hi;
            d += __shfl_xor_sync(0xffffffffu, d, 1);
            float g = d + fmaf(wi0, yf, bias);
            float act = fmaf(bb, rcpf(1.0f + ex2f(kk * g)), aa);
            if (hf == 0) sg[row] = act;
        }
        __syncthreads();   // gates ready
        if (work && tid < HID) {
            const float gi = sg[tid];
            const float gf = sg[tid + 100];
            const float gg = sg[tid + 200];
            const float go = sg[tid + 300];
            c = fmaf(gf, c, gi * gg);
            hbuf[p ^ 1][tid] = go * tanhf_fast(c);
        }
        if (wid == 4 && s >= 1) {
            // logits of step s-1 from hbuf[p] = h_{s-1}, overlapped with tail
            float acc = 0.0f;
            if (ll < NCLS) {
                const float* lwp = slw + ll * HID + ls * 25;
                const float* hp2 = &hbuf[p][ls * 25];
#pragma unroll
                for (int k = 0; k < 25; ++k)
                    acc = fmaf(lwp[k], hp2[k], acc);
            }
            acc += __shfl_xor_sync(0xffffffffu, acc, 8);
            acc += __shfl_xor_sync(0xffffffffu, acc, 16);
            if (ls == 0 && ll < NCLS)
                out[(s - 1) * NCLS + ll] = acc + slb[ll];
        }
        __syncthreads();   // h ready / logits read done
        p ^= (int)work;
    }
}

extern "C" void kernel_launch(void* const* d_in, const int* in_sizes, int n_in,
                              void* d_out, int out_size) {
    const float* x     = (const float*)d_in[0];
    const int*   y     = (const int*)  d_in[1];
    const float* eWih  = (const float*)d_in[2];
    const float* eWhh  = (const float*)d_in[3];
    const float* ebih  = (const float*)d_in[4];
    const float* ebhh  = (const float*)d_in[5];
    const float* dWih  = (const float*)d_in[6];
    const float* dWhh  = (const float*)d_in[7];
    const float* dbih  = (const float*)d_in[8];
    const float* dbhh  = (const float*)d_in[9];
    const float* linW  = (const float*)d_in[10];
    const float* linb  = (const float*)d_in[11];
    float* out = (float*)d_out;

    lstm_encdec_kernel<<<1, NTH>>>(x, y, eWih, eWhh, ebih, ebhh,
                                   dWih, dWhh, dbih, dbhh, linW, linb, out);
}

// round 5
// speedup vs baseline: 1.0264x; 1.0264x over previous
#include <cuda_runtime.h>
#include <cstdint>

#define HID   100
#define GROWS 400
#define TENC  4096
#define TDEC  4096
#define NCLS  6
#define NTH   416          // 13 warps; threads 0-399 own a gate row, 400-415 = logits lanes
#define LOG2E 1.4426950408889634f

typedef unsigned long long ull;

// precomputed input contributions (W_ih @ x + b_ih + b_hh), L2-resident
__device__ float g_gge[TENC * GROWS];   // encoder  [t][r]
__device__ float g_ggd[TDEC * GROWS];   // decoder  [s][r]

// ---- packed f32x2 helpers ----
__device__ __forceinline__ ull fma2(ull a, ull b, ull c) {
    ull d;
    asm("fma.rn.f32x2 %0, %1, %2, %3;" : "=l"(d) : "l"(a), "l"(b), "l"(c));
    return d;
}
__device__ __forceinline__ ull add2(ull a, ull b) {
    ull d;
    asm("add.rn.f32x2 %0, %1, %2;" : "=l"(d) : "l"(a), "l"(b));
    return d;
}
__device__ __forceinline__ float ex2f(float x) {
    float y; asm("ex2.approx.f32 %0, %1;" : "=f"(y) : "f"(x)); return y;
}
__device__ __forceinline__ float rcpf(float x) {
    float y; asm("rcp.approx.f32 %0, %1;" : "=f"(y) : "f"(x)); return y;
}
__device__ __forceinline__ float tanhf_fast(float x) {
    return 1.0f - 2.0f * rcpf(1.0f + ex2f((2.0f * LOG2E) * x));
}

// full-row dot: 25 independent LDS.128 (pure broadcast) + 50 FFMA2, 4 accumulators
__device__ __forceinline__ float dot100(const ull* __restrict__ w,
                                        const float* __restrict__ h) {
    const ulonglong2* hp = (const ulonglong2*)h;
    ull a0 = 0ull, a1 = 0ull, a2 = 0ull, a3 = 0ull;
#pragma unroll
    for (int m = 0; m < 25; ++m) {
        ulonglong2 hv = hp[m];           // plain load -> ptxas can batch
        if (m & 1) { a2 = fma2(w[2*m], hv.x, a2); a3 = fma2(w[2*m+1], hv.y, a3); }
        else       { a0 = fma2(w[2*m], hv.x, a0); a1 = fma2(w[2*m+1], hv.y, a1); }
    }
    ull s = add2(add2(a0, a2), add2(a1, a3));
    float lo, hi;
    asm("mov.b64 {%0, %1}, %2;" : "=f"(lo), "=f"(hi) : "l"(s));
    return lo + hi;
}

// ---------------- prep kernel: gx precompute (fully parallel) ----------------
__global__ void gx_prep_kernel(const float* __restrict__ x,     // [TENC,3]
                               const int*   __restrict__ y,     // [TDEC]
                               const float* __restrict__ eWih,  // [400,3]
                               const float* __restrict__ ebih,
                               const float* __restrict__ ebhh,
                               const float* __restrict__ dWih,  // [400,1]
                               const float* __restrict__ dbih,
                               const float* __restrict__ dbhh)
{
    int idx = blockIdx.x * blockDim.x + threadIdx.x;
    if (idx >= TENC * GROWS) return;
    int t = idx / GROWS;
    int r = idx - t * GROWS;
    g_gge[idx] = ebih[r] + ebhh[r]
               + x[3*t+0] * eWih[3*r+0]
               + x[3*t+1] * eWih[3*r+1]
               + x[3*t+2] * eWih[3*r+2];
    g_ggd[idx] = dbih[r] + dbhh[r] + (float)y[t] * dWih[r];
}

// ---------------- persistent recurrence kernel ----------------
__global__ void __launch_bounds__(NTH, 1)
lstm_encdec_kernel(const float* __restrict__ eWhh,   // [400,100]
                   const float* __restrict__ dWhh,   // [400,100]
                   const float* __restrict__ linW,   // [6,100]
                   const float* __restrict__ linb,   // [6]
                   float* __restrict__ out)          // [TDEC,6]
{
    __shared__ __align__(16) float hbuf[2][HID];    // double-buffered hidden state
    __shared__ float sg[GROWS];                      // post-activation gates
    __shared__ float slw[8 * HID];                   // lin_W copy, PADDED to 8 rows
    __shared__ float slb[NCLS];

    const int tid = threadIdx.x;
    const bool mv = (tid < GROWS);
    const int  r  = mv ? tid : 0;

    // ---- init ----
    if (tid < HID) { hbuf[0][tid] = 0.0f; hbuf[1][tid] = 0.0f; }
    if (tid < NCLS) { out[(TDEC - 1) * NCLS + tid] = 0.0f; slb[tid] = linb[tid]; }
    for (int i = tid; i < 8 * HID; i += NTH)
        slw[i] = (i < NCLS * HID) ? linW[i] : 0.0f;   // zero pad rows 6,7
    float c = 0.0f;                                  // thread j<100 owns c[j]

    // branchless activation constants (rows 200..299 = tanh)
    const bool is_tanh = (r >= 200 && r < 300);
    const float aa = is_tanh ? 1.0f : 0.0f;
    const float bb = is_tanh ? -2.0f : 1.0f;
    const float kk = is_tanh ? (2.0f * LOG2E) : (-LOG2E);

    // logits lane mapping (threads 400..415): lane idx = piece*8 + cls
    const int li    = tid - GROWS;                   // 0..15 for pad threads
    const int cls   = li & 7;
    const int piece = li >> 3;

    // ---- encoder weights -> 50 packed f32x2 registers ----
    ull w[50];
    {
        const ull* p = (const ull*)(eWhh + r * HID);
#pragma unroll
        for (int k = 0; k < 50; ++k) w[k] = p[k];
    }
    __syncthreads();

    int p = 0;

    // ================= encoder: 4096 steps =================
    float gx = mv ? g_gge[r] : 0.0f;
#pragma unroll 1
    for (int t = 0; t < TENC; ++t) {
        if (mv) {
            // prefetch next step's gx (hidden under matvec)
            const int tn = (t + 1 < TENC) ? (t + 1) : t;
            const float gx_next = g_gge[tn * GROWS + r];
            float g = dot100(w, hbuf[p]) + gx;
            sg[r] = fmaf(bb, rcpf(1.0f + ex2f(kk * g)), aa);
            gx = gx_next;
        }
        __syncthreads();   // gates ready
        if (tid < HID) {
            const float gi = sg[tid];
            const float gf = sg[tid + 100];
            const float gg = sg[tid + 200];
            const float go = sg[tid + 300];
            c = fmaf(gf, c, gi * gg);
            hbuf[p ^ 1][tid] = go * tanhf_fast(c);
        }
        __syncthreads();   // h ready
        p ^= 1;
    }

    // ---- decoder weights -> registers (one-time reload) ----
    {
        const ull* q = (const ull*)(dWhh + r * HID);
#pragma unroll
        for (int k = 0; k < 50; ++k) w[k] = q[k];
    }

    // ================= decoder: 4096 iterations =================
    // iter s: LSTM step s (s<4095) ; logits of step s-1 (s>=1) computed by the
    // 16 pad lanes in the tail window from hbuf[p] (= h_{s-1}, stable all step)
    gx = mv ? g_ggd[r] : 0.0f;
#pragma unroll 1
    for (int s = 0; s < TDEC; ++s) {
        if (mv) {
            if (s < TDEC - 1) {
                const int sn = (s + 2 < TDEC) ? (s + 1) : s;
                const float gx_next = g_ggd[sn * GROWS + r];
                float g = dot100(w, hbuf[p]) + gx;
                sg[r] = fmaf(bb, rcpf(1.0f + ex2f(kk * g)), aa);
                gx = gx_next;
            }
        }
        __syncthreads();   // gates ready
        if (tid < HID && s < TDEC - 1) {
            const float gi = sg[tid];
            const float gf = sg[tid + 100];
            const float gg = sg[tid + 200];
            const float go = sg[tid + 300];
            c = fmaf(gf, c, gi * gg);
            hbuf[p ^ 1][tid] = go * tanhf_fast(c);
        }
        if (!mv && s >= 1) {
            // logits of decoder step s-1: lin_W @ h_{s-1} + lin_b
            // cls 6,7 read zero-padded rows (harmless, in-bounds)
            float acc = 0.0f;
            const float* lwp = slw + cls * HID + piece * 50;
            const float* hp  = &hbuf[p][piece * 50];
#pragma unroll
            for (int k = 0; k < 50; ++k)
                acc = fmaf(lwp[k], hp[k], acc);
            // combine pieces: lane 16+cls <-> lane 24+cls
            acc += __shfl_xor_sync(0xFFFF0000u, acc, 8);
            if (piece == 0 && cls < NCLS)
                out[(s - 1) * NCLS + cls] = acc + slb[cls];
        }
        __syncthreads();   // h ready / logits read done
        if (s < TDEC - 1) p ^= 1;
    }
}

extern "C" void kernel_launch(void* const* d_in, const int* in_sizes, int n_in,
                              void* d_out, int out_size) {
    const float* x     = (const float*)d_in[0];
    const int*   y     = (const int*)  d_in[1];
    const float* eWih  = (const float*)d_in[2];
    const float* eWhh  = (const float*)d_in[3];
    const float* ebih  = (const float*)d_in[4];
    const float* ebhh  = (const float*)d_in[5];
    const float* dWih  = (const float*)d_in[6];
    const float* dWhh  = (const float*)d_in[7];
    const float* dbih  = (const float*)d_in[8];
    const float* dbhh  = (const float*)d_in[9];
    const float* linW  = (const float*)d_in[10];
    const float* linb  = (const float*)d_in[11];
    float* out = (float*)d_out;

    const int n = TENC * GROWS;
    gx_prep_kernel<<<(n + 255) / 256, 256>>>(x, y, eWih, ebih, ebhh,
                                             dWih, dbih, dbhh);
    lstm_encdec_kernel<<<1, NTH>>>(eWhh, dWhh, linW, linb, out);
}

// round 6
// speedup vs baseline: 1.4276x; 1.3909x over previous
#include <cuda_runtime.h>
#include <cstdint>

#define HID   100
#define GROWS 400
#define TENC  4096
#define TDEC  4096
#define NCLS  6
#define NTH   256          // 8 warps: threads 0-199 = matvec (2 rows each), warp 7 = logits
#define LOG2E 1.4426950408889634f

typedef unsigned long long ull;

// precomputed input contributions (W_ih @ x + b_ih + b_hh), L2-resident
__device__ float g_gge[TENC * GROWS];   // encoder  [t][r]
__device__ float g_ggd[TDEC * GROWS];   // decoder  [s][r]

// ---- packed f32x2 helpers ----
__device__ __forceinline__ ull fma2(ull a, ull b, ull c) {
    ull d;
    asm("fma.rn.f32x2 %0, %1, %2, %3;" : "=l"(d) : "l"(a), "l"(b), "l"(c));
    return d;
}
__device__ __forceinline__ ull add2(ull a, ull b) {
    ull d;
    asm("add.rn.f32x2 %0, %1, %2;" : "=l"(d) : "l"(a), "l"(b));
    return d;
}
__device__ __forceinline__ float ex2f(float x) {
    float y; asm("ex2.approx.f32 %0, %1;" : "=f"(y) : "f"(x)); return y;
}
__device__ __forceinline__ float rcpf(float x) {
    float y; asm("rcp.approx.f32 %0, %1;" : "=f"(y) : "f"(x)); return y;
}
__device__ __forceinline__ float tanhf_fast(float x) {
    return 1.0f - 2.0f * rcpf(1.0f + ex2f((2.0f * LOG2E) * x));
}

// Two dots sharing each h load (4 FFMA2 per LDS.128), 4-deep pipelined.
__device__ __forceinline__ void dotpair(const ull (&w1)[50], const ull (&w2)[50],
                                        unsigned hb, float gx1, float gx2,
                                        float& d1, float& d2) {
    ull bxa[4], bya[4];
#pragma unroll
    for (int m = 0; m < 4; ++m)
        asm volatile("ld.shared.v2.b64 {%0,%1},[%2];"
                     : "=l"(bxa[m]), "=l"(bya[m]) : "r"(hb + 16u * m));
    ull p0, p1 = 0ull, q0, q1 = 0ull;
    asm("mov.b64 %0,{%1,%2};" : "=l"(p0) : "f"(gx1), "f"(0.0f));
    asm("mov.b64 %0,{%1,%2};" : "=l"(q0) : "f"(gx2), "f"(0.0f));
#pragma unroll
    for (int m = 0; m < 25; ++m) {
        const int sl = m & 3;
        p0 = fma2(w1[2*m],     bxa[sl], p0);
        p1 = fma2(w1[2*m + 1], bya[sl], p1);
        q0 = fma2(w2[2*m],     bxa[sl], q0);
        q1 = fma2(w2[2*m + 1], bya[sl], q1);
        if (m + 4 < 25)
            asm volatile("ld.shared.v2.b64 {%0,%1},[%2];"
                         : "=l"(bxa[sl]), "=l"(bya[sl]) : "r"(hb + 16u * (m + 4)));
    }
    ull s1 = add2(p0, p1), s2 = add2(q0, q1);
    float a, b, e, f;
    asm("mov.b64 {%0,%1},%2;" : "=f"(a), "=f"(b) : "l"(s1));
    asm("mov.b64 {%0,%1},%2;" : "=f"(e), "=f"(f) : "l"(s2));
    d1 = a + b;
    d2 = e + f;
}

// ---------------- prep kernel: gx precompute (fully parallel) ----------------
__global__ void gx_prep_kernel(const float* __restrict__ x,     // [TENC,3]
                               const int*   __restrict__ y,     // [TDEC]
                               const float* __restrict__ eWih,  // [400,3]
                               const float* __restrict__ ebih,
                               const float* __restrict__ ebhh,
                               const float* __restrict__ dWih,  // [400,1]
                               const float* __restrict__ dbih,
                               const float* __restrict__ dbhh)
{
    int idx = blockIdx.x * blockDim.x + threadIdx.x;
    if (idx >= TENC * GROWS) return;
    int t = idx / GROWS;
    int r = idx - t * GROWS;
    g_gge[idx] = ebih[r] + ebhh[r]
               + x[3*t+0] * eWih[3*r+0]
               + x[3*t+1] * eWih[3*r+1]
               + x[3*t+2] * eWih[3*r+2];
    g_ggd[idx] = dbih[r] + dbhh[r] + (float)y[t] * dWih[r];
}

// One recurrence phase (encoder or decoder), fully inlined.
template<bool DEC>
__device__ __forceinline__ void run_phase(
    int T, const float* __restrict__ gg,
    ull (&w1)[50], ull (&w2)[50],
    float& c, int& p, unsigned& hbp,
    float (&hbuf)[2][128], float* sgf, float* sgo,
    const float* slw, const float* slb, float* __restrict__ out,
    int tid, float aa2, float bb2, float kk2)
{
    const bool mv   = (tid < 200);
    const bool upd  = (tid < HID);
    const bool lwrp = ((tid >> 5) == 7);      // logits warp (threads 224-255)
    const int lane  = tid & 31;
    const int cls   = lane & 7;
    const int piece = lane >> 3;              // 4 pieces of 25

#pragma unroll 1
    for (int s = 0; s < T; ++s) {
        const bool work = (!DEC) || (s < T - 1);
        float gi = 0.0f, ggv = 0.0f;
        if (mv && work) {
            const float gx1 = __ldg(gg + s * GROWS + tid);
            const float gx2 = __ldg(gg + s * GROWS + tid + 200);
            float d1, d2;
            dotpair(w1, w2, hbp, gx1, gx2, d1, d2);
            // row1 (0..199 = i or f): always sigmoid
            const float act1 = rcpf(1.0f + ex2f(-LOG2E * d1));
            // row2 (200..399): tanh for tid<100 (g), sigmoid for tid>=100 (o)
            const float act2 = fmaf(bb2, rcpf(1.0f + ex2f(kk2 * d2)), aa2);
            if (tid < HID) { gi = act1; ggv = act2; }          // keep in regs
            else           { sgf[tid - HID] = act1; sgo[tid - HID] = act2; }
        }
        if (DEC && lwrp && s >= 1) {
            // logits of step s-1 from hbuf[p] = h_{s-1}, overlapped with matvec
            float acc = 0.0f;
            const float* lp = slw + cls * HID + piece * 25;    // cls 6,7 hit zero pad
            const float* hp = &hbuf[p][piece * 25];
#pragma unroll
            for (int k = 0; k < 25; ++k)
                acc = fmaf(lp[k], hp[k], acc);
            acc += __shfl_xor_sync(0xffffffffu, acc, 8);
            acc += __shfl_xor_sync(0xffffffffu, acc, 16);
            if (piece == 0 && cls < NCLS)
                out[(s - 1) * NCLS + cls] = acc + slb[cls];
        }
        __syncthreads();   // gates ready (and logits done reading hbuf[p])
        if (upd && work) {
            const float gf = sgf[tid];
            const float go = sgo[tid];
            c = fmaf(gf, c, gi * ggv);
            hbuf[p ^ 1][tid] = go * tanhf_fast(c);
        }
        __syncthreads();   // h ready
        if (work) { p ^= 1; hbp ^= 512u; }
    }
}

// ---------------- persistent recurrence kernel ----------------
__global__ void __launch_bounds__(NTH, 1)
lstm_encdec_kernel(const float* __restrict__ eWhh,   // [400,100]
                   const float* __restrict__ dWhh,   // [400,100]
                   const float* __restrict__ linW,   // [6,100]
                   const float* __restrict__ linb,   // [6]
                   float* __restrict__ out)          // [TDEC,6]
{
    __shared__ __align__(16) float hbuf[2][128];     // padded rows (512B) for ^512 flip
    __shared__ float sgf[HID], sgo[HID];             // f and o gates only
    __shared__ float slw[8 * HID];                   // lin_W padded to 8 rows
    __shared__ float slb[NCLS];

    const int tid = threadIdx.x;

    // ---- init ----
    if (tid < HID) { hbuf[0][tid] = 0.0f; hbuf[1][tid] = 0.0f; }
    if (tid < NCLS) { out[(TDEC - 1) * NCLS + tid] = 0.0f; slb[tid] = linb[tid]; }
    for (int i = tid; i < 8 * HID; i += NTH)
        slw[i] = (i < NCLS * HID) ? linW[i] : 0.0f;
    float c = 0.0f;                                  // thread j<100 owns c[j]

    // act constants for row2 = tid+200: tanh if tid<100 else sigmoid
    const bool t2 = (tid < 100);
    const float aa2 = t2 ? 1.0f : 0.0f;
    const float bb2 = t2 ? -2.0f : 1.0f;
    const float kk2 = t2 ? (2.0f * LOG2E) : (-LOG2E);

    // ---- encoder weights: rows tid and tid+200 (200 regs) ----
    ull w1[50], w2[50];
    if (tid < 200) {
        const ull* p1 = (const ull*)(eWhh + tid * HID);
        const ull* p2 = (const ull*)(eWhh + (tid + 200) * HID);
#pragma unroll
        for (int k = 0; k < 50; ++k) { w1[k] = p1[k]; w2[k] = p2[k]; }
    }
    __syncthreads();

    int p = 0;
    unsigned hbp = (unsigned)__cvta_generic_to_shared(&hbuf[0][0]);

    // ================= encoder =================
    run_phase<false>(TENC, g_gge, w1, w2, c, p, hbp, hbuf, sgf, sgo,
                     slw, slb, out, tid, aa2, bb2, kk2);

    // ---- decoder weights (one-time reload) ----
    if (tid < 200) {
        const ull* p1 = (const ull*)(dWhh + tid * HID);
        const ull* p2 = (const ull*)(dWhh + (tid + 200) * HID);
#pragma unroll
        for (int k = 0; k < 50; ++k) { w1[k] = p1[k]; w2[k] = p2[k]; }
    }
    // registers only -> no barrier needed

    // ================= decoder =================
    run_phase<true>(TDEC, g_ggd, w1, w2, c, p, hbp, hbuf, sgf, sgo,
                    slw, slb, out, tid, aa2, bb2, kk2);
}

extern "C" void kernel_launch(void* const* d_in, const int* in_sizes, int n_in,
                              void* d_out, int out_size) {
    const float* x     = (const float*)d_in[0];
    const int*   y     = (const int*)  d_in[1];
    const float* eWih  = (const float*)d_in[2];
    const float* eWhh  = (const float*)d_in[3];
    const float* ebih  = (const float*)d_in[4];
    const float* ebhh  = (const float*)d_in[5];
    const float* dWih  = (const float*)d_in[6];
    const float* dWhh  = (const float*)d_in[7];
    const float* dbih  = (const float*)d_in[8];
    const float* dbhh  = (const float*)d_in[9];
    const float* linW  = (const float*)d_in[10];
    const float* linb  = (const float*)d_in[11];
    float* out = (float*)d_out;

    const int n = TENC * GROWS;
    gx_prep_kernel<<<(n + 255) / 256, 256>>>(x, y, eWih, ebih, ebhh,
                                             dWih, dbih, dbhh);
    lstm_encdec_kernel<<<1, NTH>>>(eWhh, dWhh, linW, linb, out);
}

// round 7
// speedup vs baseline: 1.9364x; 1.3564x over previous
#include <cuda_runtime.h>
#include <cstdint>

#define HID   100
#define GROWS 400
#define TENC  4096
#define TDEC  4096
#define NCLS  6
#define NTH   256          // 8 warps: threads 0-199 = matvec (2 rows each), warp 7 = logits
#define LOG2E 1.4426950408889634f

typedef unsigned long long ull;

// precomputed input contributions, packed: [t][pair r][2] = rows (r, r+200)
__device__ float g_gge[TENC * GROWS];   // encoder
__device__ float g_ggd[TDEC * GROWS];   // decoder

// ---- packed f32x2 helpers ----
__device__ __forceinline__ ull fma2(ull a, ull b, ull c) {
    ull d;
    asm("fma.rn.f32x2 %0, %1, %2, %3;" : "=l"(d) : "l"(a), "l"(b), "l"(c));
    return d;
}
__device__ __forceinline__ ull add2(ull a, ull b) {
    ull d;
    asm("add.rn.f32x2 %0, %1, %2;" : "=l"(d) : "l"(a), "l"(b));
    return d;
}
__device__ __forceinline__ float ex2f(float x) {
    float y; asm("ex2.approx.f32 %0, %1;" : "=f"(y) : "f"(x)); return y;
}
__device__ __forceinline__ float rcpf(float x) {
    float y; asm("rcp.approx.f32 %0, %1;" : "=f"(y) : "f"(x)); return y;
}
__device__ __forceinline__ float tanhf_fast(float x) {
    return 1.0f - 2.0f * rcpf(1.0f + ex2f((2.0f * LOG2E) * x));
}

// Two dots sharing each h load (4 FFMA2 per LDS.128), 4-deep pipelined.
// gx1/gx2 are REGISTERS (prefetched) -> no memory wait at chain head.
__device__ __forceinline__ void dotpair(const ull (&w1)[50], const ull (&w2)[50],
                                        unsigned hb, float gx1, float gx2,
                                        float& d1, float& d2) {
    ull bxa[4], bya[4];
#pragma unroll
    for (int m = 0; m < 4; ++m)
        asm volatile("ld.shared.v2.b64 {%0,%1},[%2];"
                     : "=l"(bxa[m]), "=l"(bya[m]) : "r"(hb + 16u * m));
    ull p0, p1 = 0ull, q0, q1 = 0ull;
    asm("mov.b64 %0,{%1,%2};" : "=l"(p0) : "f"(gx1), "f"(0.0f));
    asm("mov.b64 %0,{%1,%2};" : "=l"(q0) : "f"(gx2), "f"(0.0f));
#pragma unroll
    for (int m = 0; m < 25; ++m) {
        const int sl = m & 3;
        p0 = fma2(w1[2*m],     bxa[sl], p0);
        p1 = fma2(w1[2*m + 1], bya[sl], p1);
        q0 = fma2(w2[2*m],     bxa[sl], q0);
        q1 = fma2(w2[2*m + 1], bya[sl], q1);
        if (m + 4 < 25)
            asm volatile("ld.shared.v2.b64 {%0,%1},[%2];"
                         : "=l"(bxa[sl]), "=l"(bya[sl]) : "r"(hb + 16u * (m + 4)));
    }
    ull s1 = add2(p0, p1), s2 = add2(q0, q1);
    float a, b, e, f;
    asm("mov.b64 {%0,%1},%2;" : "=f"(a), "=f"(b) : "l"(s1));
    asm("mov.b64 {%0,%1},%2;" : "=f"(e), "=f"(f) : "l"(s2));
    d1 = a + b;
    d2 = e + f;
}

// ---------------- prep kernel: gx precompute (fully parallel) ----------------
__global__ void gx_prep_kernel(const float* __restrict__ x,     // [TENC,3]
                               const int*   __restrict__ y,     // [TDEC]
                               const float* __restrict__ eWih,  // [400,3]
                               const float* __restrict__ ebih,
                               const float* __restrict__ ebhh,
                               const float* __restrict__ dWih,  // [400,1]
                               const float* __restrict__ dbih,
                               const float* __restrict__ dbhh)
{
    int idx = blockIdx.x * blockDim.x + threadIdx.x;
    if (idx >= TENC * GROWS) return;
    int t = idx / GROWS;
    int r = idx - t * GROWS;
    // packed layout: [t][r%200][2] with last index = r/200
    int dst = t * GROWS + (r % 200) * 2 + (r / 200);
    g_gge[dst] = ebih[r] + ebhh[r]
               + x[3*t+0] * eWih[3*r+0]
               + x[3*t+1] * eWih[3*r+1]
               + x[3*t+2] * eWih[3*r+2];
    g_ggd[dst] = dbih[r] + dbhh[r] + (float)y[t] * dWih[r];
}

// One recurrence phase (encoder or decoder), fully inlined.
template<bool DEC>
__device__ __forceinline__ void run_phase(
    int T, const float* __restrict__ gg,
    ull (&w1)[50], ull (&w2)[50],
    float& c, int& p, unsigned& hbp,
    float (&hbuf)[2][128], float2* sfo,
    const float* slw, const float* slb, float* __restrict__ out,
    int tid, float aa2, float bb2, float kk2)
{
    const bool mv   = (tid < 200);
    const bool upd  = (tid < HID);
    const bool lwrp = ((tid >> 5) == 7);      // logits warp (threads 224-255)
    const int lane  = tid & 31;
    const int cls   = lane & 7;
    const int piece = lane >> 3;              // 4 pieces of 25

    // prologue: gx for step 0 already in registers
    float2 gx = make_float2(0.0f, 0.0f);
    if (mv) gx = __ldg(((const float2*)gg) + tid);

#pragma unroll 1
    for (int s = 0; s < T; ++s) {
        const bool work = (!DEC) || (s < T - 1);
        float ig = 0.0f;
        float2 fo_self;
        if (mv && work) {
            // prefetch next step's gx (hidden under the matvec below)
            const int sn = s + 1;
            const bool nvalid = DEC ? (sn < T - 1) : (sn < T);
            float2 nx = make_float2(0.0f, 0.0f);
            if (nvalid) nx = __ldg(((const float2*)(gg + sn * GROWS)) + tid);

            float d1, d2;
            dotpair(w1, w2, hbp, gx.x, gx.y, d1, d2);
            // row1 (tid): i (tid<100) or f -> sigmoid
            const float act1 = rcpf(1.0f + ex2f(-LOG2E * d1));
            // row2 (tid+200): g (tanh) for tid<100, o (sigmoid) otherwise
            const float act2 = fmaf(bb2, rcpf(1.0f + ex2f(kk2 * d2)), aa2);
            if (tid < HID) {
                ig = act1 * act2;                     // i*g stays in regs
            } else {
                sfo[tid - HID] = make_float2(act1, act2);   // {f, o} one STS.64
            }
            gx = nx;
        }
        if (DEC && lwrp && s >= 1) {
            // logits of step s-1 from hbuf[p] = h_{s-1}, overlapped with matvec
            float acc = 0.0f;
            const float* lp = slw + cls * HID + piece * 25;    // cls 6,7 hit zero pad
            const float* hp = &hbuf[p][piece * 25];
#pragma unroll
            for (int k = 0; k < 25; ++k)
                acc = fmaf(lp[k], hp[k], acc);
            acc += __shfl_xor_sync(0xffffffffu, acc, 8);
            acc += __shfl_xor_sync(0xffffffffu, acc, 16);
            if (piece == 0 && cls < NCLS)
                out[(s - 1) * NCLS + cls] = acc + slb[cls];
        }
        __syncthreads();   // gates ready (and logits done reading hbuf[p])
        if (upd && work) {
            const float2 fo = sfo[tid];               // one LDS.64: {f, o}
            c = fmaf(fo.x, c, ig);
            hbuf[p ^ 1][tid] = fo.y * tanhf_fast(c);
        }
        __syncthreads();   // h ready
        if (work) { p ^= 1; hbp ^= 512u; }
        (void)fo_self;
    }
}

// ---------------- persistent recurrence kernel ----------------
__global__ void __launch_bounds__(NTH, 1)
lstm_encdec_kernel(const float* __restrict__ eWhh,   // [400,100]
                   const float* __restrict__ dWhh,   // [400,100]
                   const float* __restrict__ linW,   // [6,100]
                   const float* __restrict__ linb,   // [6]
                   float* __restrict__ out)          // [TDEC,6]
{
    __shared__ __align__(1024) float hbuf[2][128];   // 512B rows -> ^512 flip valid
    __shared__ __align__(8) float2 sfo[HID];         // {f,o} gate pairs
    __shared__ float slw[8 * HID];                   // lin_W padded to 8 rows
    __shared__ float slb[NCLS];

    const int tid = threadIdx.x;

    // ---- init ----
    if (tid < HID) { hbuf[0][tid] = 0.0f; hbuf[1][tid] = 0.0f; }
    if (tid < NCLS) { out[(TDEC - 1) * NCLS + tid] = 0.0f; slb[tid] = linb[tid]; }
    for (int i = tid; i < 8 * HID; i += NTH)
        slw[i] = (i < NCLS * HID) ? linW[i] : 0.0f;
    float c = 0.0f;                                  // thread j<100 owns c[j]

    // act constants for row2 = tid+200: tanh if tid<100 else sigmoid
    const bool t2 = (tid < 100);
    const float aa2 = t2 ? 1.0f : 0.0f;
    const float bb2 = t2 ? -2.0f : 1.0f;
    const float kk2 = t2 ? (2.0f * LOG2E) : (-LOG2E);

    // ---- encoder weights: rows tid and tid+200 (200 regs) ----
    ull w1[50], w2[50];
    if (tid < 200) {
        const ull* p1 = (const ull*)(eWhh + tid * HID);
        const ull* p2 = (const ull*)(eWhh + (tid + 200) * HID);
#pragma unroll
        for (int k = 0; k < 50; ++k) { w1[k] = p1[k]; w2[k] = p2[k]; }
    }
    __syncthreads();

    int p = 0;
    unsigned hbp = (unsigned)__cvta_generic_to_shared(&hbuf[0][0]);

    // ================= encoder =================
    run_phase<false>(TENC, g_gge, w1, w2, c, p, hbp, hbuf, sfo,
                     slw, slb, out, tid, aa2, bb2, kk2);

    // ---- decoder weights (one-time reload) ----
    if (tid < 200) {
        const ull* p1 = (const ull*)(dWhh + tid * HID);
        const ull* p2 = (const ull*)(dWhh + (tid + 200) * HID);
#pragma unroll
        for (int k = 0; k < 50; ++k) { w1[k] = p1[k]; w2[k] = p2[k]; }
    }
    // registers only -> no barrier needed

    // ================= decoder =================
    run_phase<true>(TDEC, g_ggd, w1, w2, c, p, hbp, hbuf, sfo,
                    slw, slb, out, tid, aa2, bb2, kk2);
}

extern "C" void kernel_launch(void* const* d_in, const int* in_sizes, int n_in,
                              void* d_out, int out_size) {
    const float* x     = (const float*)d_in[0];
    const int*   y     = (const int*)  d_in[1];
    const float* eWih  = (const float*)d_in[2];
    const float* eWhh  = (const float*)d_in[3];
    const float* ebih  = (const float*)d_in[4];
    const float* ebhh  = (const float*)d_in[5];
    const float* dWih  = (const float*)d_in[6];
    const float* dWhh  = (const float*)d_in[7];
    const float* dbih  = (const float*)d_in[8];
    const float* dbhh  = (const float*)d_in[9];
    const float* linW  = (const float*)d_in[10];
    const float* linb  = (const float*)d_in[11];
    float* out = (float*)d_out;

    const int n = TENC * GROWS;
    gx_prep_kernel<<<(n + 255) / 256, 256>>>(x, y, eWih, ebih, ebhh,
                                             dWih, dbih, dbhh);
    lstm_encdec_kernel<<<1, NTH>>>(eWhh, dWhh, linW, linb, out);
}

// round 8
// speedup vs baseline: 1.9828x; 1.0239x over previous
#include <cuda_runtime.h>
#include <cstdint>

#define HID   100
#define GROWS 400
#define TENC  4096
#define TDEC  4096
#define NCLS  6
#define NTH   256          // 8 warps: threads 0-199 matvec (2 rows each), warp 7 logits
#define LOG2E 1.4426950408889634f

typedef unsigned long long ull;

// precomputed input contributions, packed per-thread:
// thread t (j=t>>1): slot0 = row (j + (t&1)*100)  [i or f]
//                    slot1 = row (j + (t&1)*100 + 200) [g or o]
__device__ float g_gge[TENC * GROWS];   // encoder
__device__ float g_ggd[TDEC * GROWS];   // decoder

// ---- packed f32x2 helpers ----
__device__ __forceinline__ ull fma2(ull a, ull b, ull c) {
    ull d;
    asm("fma.rn.f32x2 %0, %1, %2, %3;" : "=l"(d) : "l"(a), "l"(b), "l"(c));
    return d;
}
__device__ __forceinline__ ull add2(ull a, ull b) {
    ull d;
    asm("add.rn.f32x2 %0, %1, %2;" : "=l"(d) : "l"(a), "l"(b));
    return d;
}
__device__ __forceinline__ float ex2f(float x) {
    float y; asm("ex2.approx.f32 %0, %1;" : "=f"(y) : "f"(x)); return y;
}
__device__ __forceinline__ float rcpf(float x) {
    float y; asm("rcp.approx.f32 %0, %1;" : "=f"(y) : "f"(x)); return y;
}
__device__ __forceinline__ float tanhf_fast(float x) {
    return 1.0f - 2.0f * rcpf(1.0f + ex2f((2.0f * LOG2E) * x));
}

// Two dots sharing each h load (4 FFMA2 per LDS.128), 4-deep pipelined.
__device__ __forceinline__ void dotpair(const ull (&w1)[50], const ull (&w2)[50],
                                        unsigned hb, float gx1, float gx2,
                                        float& d1, float& d2) {
    ull bxa[4], bya[4];
#pragma unroll
    for (int m = 0; m < 4; ++m)
        asm volatile("ld.shared.v2.b64 {%0,%1},[%2];"
                     : "=l"(bxa[m]), "=l"(bya[m]) : "r"(hb + 16u * m));
    ull p0, p1 = 0ull, q0, q1 = 0ull;
    asm("mov.b64 %0,{%1,%2};" : "=l"(p0) : "f"(gx1), "f"(0.0f));
    asm("mov.b64 %0,{%1,%2};" : "=l"(q0) : "f"(gx2), "f"(0.0f));
#pragma unroll
    for (int m = 0; m < 25; ++m) {
        const int sl = m & 3;
        p0 = fma2(w1[2*m],     bxa[sl], p0);
        p1 = fma2(w1[2*m + 1], bya[sl], p1);
        q0 = fma2(w2[2*m],     bxa[sl], q0);
        q1 = fma2(w2[2*m + 1], bya[sl], q1);
        if (m + 4 < 25)
            asm volatile("ld.shared.v2.b64 {%0,%1},[%2];"
                         : "=l"(bxa[sl]), "=l"(bya[sl]) : "r"(hb + 16u * (m + 4)));
    }
    ull s1 = add2(p0, p1), s2 = add2(q0, q1);
    float a, b, e, f;
    asm("mov.b64 {%0,%1},%2;" : "=f"(a), "=f"(b) : "l"(s1));
    asm("mov.b64 {%0,%1},%2;" : "=f"(e), "=f"(f) : "l"(s2));
    d1 = a + b;
    d2 = e + f;
}

// ---------------- prep kernel: gx precompute (fully parallel) ----------------
__global__ void gx_prep_kernel(const float* __restrict__ x,     // [TENC,3]
                               const int*   __restrict__ y,     // [TDEC]
                               const float* __restrict__ eWih,  // [400,3]
                               const float* __restrict__ ebih,
                               const float* __restrict__ ebhh,
                               const float* __restrict__ dWih,  // [400,1]
                               const float* __restrict__ dbih,
                               const float* __restrict__ dbhh)
{
    int idx = blockIdx.x * blockDim.x + threadIdx.x;
    if (idx >= TENC * GROWS) return;
    int t = idx / GROWS;
    int r = idx - t * GROWS;
    // even/odd per-thread packing:
    //   r<100:  thr=2r,          slot 0   (i)
    //   <200:   thr=2(r-100)+1,  slot 0   (f)
    //   <300:   thr=2(r-200),    slot 1   (g)
    //   else:   thr=2(r-300)+1,  slot 1   (o)
    int rm = r % 100, blk = r / 100;
    int thr  = 2 * rm + (blk & 1);
    int slot = blk >> 1;
    int dst = t * GROWS + thr * 2 + slot;
    g_gge[dst] = ebih[r] + ebhh[r]
               + x[3*t+0] * eWih[3*r+0]
               + x[3*t+1] * eWih[3*r+1]
               + x[3*t+2] * eWih[3*r+2];
    g_ggd[dst] = dbih[r] + dbhh[r] + (float)y[t] * dWih[r];
}

// One recurrence phase (encoder or decoder), fully inlined.
template<bool DEC>
__device__ __forceinline__ void run_phase(
    int T, const float* __restrict__ gg,
    ull (&w1)[50], ull (&w2)[50],
    float& c, int& p, unsigned& hbp,
    float (&hbuf)[2][128],
    const float* slw, const float* slb, float* __restrict__ out,
    int tid, unsigned mvmask, float aa2, float bb2, float kk2)
{
    const bool mv   = (tid < 200);
    const bool ev   = !(tid & 1);
    const int  j    = tid >> 1;
    const bool lwrp = ((tid >> 5) == 7);      // logits warp (threads 224-255)
    const int lane  = tid & 31;
    const int cls   = lane & 7;
    const int piece = lane >> 3;              // 4 pieces of 25

    // gx for step 0 already in registers
    float2 gx = make_float2(0.0f, 0.0f);
    if (mv) gx = __ldg(((const float2*)gg) + tid);

#pragma unroll 1
    for (int s = 0; s < T; ++s) {
        const bool work = (!DEC) || (s < T - 1);
        if (mv && work) {
            // prefetch next step's gx (hidden under the matvec below)
            const int sn = s + 1;
            const bool nvalid = DEC ? (sn < T - 1) : (sn < T);
            float2 nx = gx;
            if (nvalid) nx = __ldg(((const float2*)(gg + sn * GROWS)) + tid);

            float d1, d2;
            dotpair(w1, w2, hbp, gx.x, gx.y, d1, d2);
            // slot0: i (even) or f (odd) -> always sigmoid
            const float act1 = rcpf(1.0f + ex2f(-LOG2E * d1));
            // slot1: g (even, tanh) or o (odd, sigmoid)
            const float act2 = fmaf(bb2, rcpf(1.0f + ex2f(kk2 * d2)), aa2);
            // exchange with neighbor: even gets {f,o}, odd gets {i,g} (unused)
            const float pf = __shfl_xor_sync(mvmask, act1, 1);
            const float po = __shfl_xor_sync(mvmask, act2, 1);
            if (ev) {
                c = fmaf(pf, c, act1 * act2);          // c = f*c + i*g
                hbuf[p ^ 1][j] = po * tanhf_fast(c);   // h = o*tanh(c)
            }
            gx = nx;
        }
        if (DEC && lwrp && s >= 1) {
            // logits of step s-1 from hbuf[p] = h_{s-1}, overlapped with matvec
            float acc = 0.0f;
            const float* lp = slw + cls * HID + piece * 25;    // cls 6,7 hit zero pad
            const float* hp = &hbuf[p][piece * 25];
#pragma unroll
            for (int k = 0; k < 25; ++k)
                acc = fmaf(lp[k], hp[k], acc);
            acc += __shfl_xor_sync(0xffffffffu, acc, 8);
            acc += __shfl_xor_sync(0xffffffffu, acc, 16);
            if (piece == 0 && cls < NCLS)
                out[(s - 1) * NCLS + cls] = acc + slb[cls];
        }
        __syncthreads();   // single barrier: h_{p^1} complete, hbuf[p] readers done
        if (work) { p ^= 1; hbp ^= 512u; }
    }
}

// ---------------- persistent recurrence kernel ----------------
__global__ void __launch_bounds__(NTH, 1)
lstm_encdec_kernel(const float* __restrict__ eWhh,   // [400,100]
                   const float* __restrict__ dWhh,   // [400,100]
                   const float* __restrict__ linW,   // [6,100]
                   const float* __restrict__ linb,   // [6]
                   float* __restrict__ out)          // [TDEC,6]
{
    __shared__ __align__(1024) float hbuf[2][128];   // 512B rows -> ^512 flip valid
    __shared__ float slw[8 * HID];                   // lin_W padded to 8 rows
    __shared__ float slb[NCLS];

    const int tid = threadIdx.x;
    const int wid = tid >> 5;

    // ---- init ----
    if (tid < HID) { hbuf[0][tid] = 0.0f; hbuf[1][tid] = 0.0f; }
    if (tid < NCLS) { out[(TDEC - 1) * NCLS + tid] = 0.0f; slb[tid] = linb[tid]; }
    for (int i = tid; i < 8 * HID; i += NTH)
        slw[i] = (i < NCLS * HID) ? linW[i] : 0.0f;
    float c = 0.0f;                                  // even thread t owns c[t>>1]

    // shfl participation mask for the mv branch
    const unsigned mvmask = (wid == 6) ? 0xFFu : 0xFFFFFFFFu;

    // act2 constants: even -> tanh (g), odd -> sigmoid (o)
    const bool ev = !(tid & 1);
    const float aa2 = ev ? 1.0f : 0.0f;
    const float bb2 = ev ? -2.0f : 1.0f;
    const float kk2 = ev ? (2.0f * LOG2E) : (-LOG2E);

    // row indices for this thread: r1 = i/f row, r2 = g/o row
    const int j  = tid >> 1;
    const int r1 = j + (tid & 1) * 100;
    const int r2 = r1 + 200;

    // ---- encoder weights (200 regs) ----
    ull w1[50], w2[50];
    if (tid < 200) {
        const ull* p1 = (const ull*)(eWhh + r1 * HID);
        const ull* p2 = (const ull*)(eWhh + r2 * HID);
#pragma unroll
        for (int k = 0; k < 50; ++k) { w1[k] = p1[k]; w2[k] = p2[k]; }
    }
    __syncthreads();

    int p = 0;
    unsigned hbp = (unsigned)__cvta_generic_to_shared(&hbuf[0][0]);

    // ================= encoder =================
    run_phase<false>(TENC, g_gge, w1, w2, c, p, hbp, hbuf,
                     slw, slb, out, tid, mvmask, aa2, bb2, kk2);

    // ---- decoder weights (one-time reload, registers only) ----
    if (tid < 200) {
        const ull* p1 = (const ull*)(dWhh + r1 * HID);
        const ull* p2 = (const ull*)(dWhh + r2 * HID);
#pragma unroll
        for (int k = 0; k < 50; ++k) { w1[k] = p1[k]; w2[k] = p2[k]; }
    }

    // ================= decoder =================
    run_phase<true>(TDEC, g_ggd, w1, w2, c, p, hbp, hbuf,
                    slw, slb, out, tid, mvmask, aa2, bb2, kk2);
}

extern "C" void kernel_launch(void* const* d_in, const int* in_sizes, int n_in,
                              void* d_out, int out_size) {
    const float* x     = (const float*)d_in[0];
    const int*   y     = (const int*)  d_in[1];
    const float* eWih  = (const float*)d_in[2];
    const float* eWhh  = (const float*)d_in[3];
    const float* ebih  = (const float*)d_in[4];
    const float* ebhh  = (const float*)d_in[5];
    const float* dWih  = (const float*)d_in[6];
    const float* dWhh  = (const float*)d_in[7];
    const float* dbih  = (const float*)d_in[8];
    const float* dbhh  = (const float*)d_in[9];
    const float* linW  = (const float*)d_in[10];
    const float* linb  = (const float*)d_in[11];
    float* out = (float*)d_out;

    const int n = TENC * GROWS;
    gx_prep_kernel<<<(n + 255) / 256, 256>>>(x, y, eWih, ebih, ebhh,
                                             dWih, dbih, dbhh);
    lstm_encdec_kernel<<<1, NTH>>>(eWhh, dWhh, linW, linb, out);
}